// round 14
// baseline (speedup 1.0000x reference)
#include <cuda_runtime.h>
#include <cuda_fp16.h>
#include <math.h>
#include <cstdint>

#define NN 50000
#define EE 800000
#define DD 128
#define PAD 272                 // padded smem row stride (bytes): conflict-free ldmatrix
#define SA 0
#define SW 34816
#define SM_TOT 69632
#define CHUNK 1024

// ---- scratch (__device__ globals; allocation-free rule) ----
__device__ __half g_hwsA[(size_t)NN * DD];   // (h@W)*dinv fp16, ping
__device__ __half g_hwsB[(size_t)NN * DD];   // ... pong
__device__ int    g_count[NN];
__device__ float  g_dinv[NN];
__device__ int    g_rowptr[NN];              // segment start (arrival-ordered)
__device__ int    g_cursor[NN];
__device__ int    g_adj[EE];
__device__ int    g_scanbase;                // global cursor for chunk bases
__device__ __half g_wt[3 * DD * DD];         // W^T fp16 ([n][k] row-major)

// ---- helpers ----
__device__ __forceinline__ uint32_t smem_u32(const void* p) {
    uint32_t a;
    asm("{ .reg .u64 t; cvta.to.shared.u64 t, %1; cvt.u32.u64 %0, t; }" : "=r"(a) : "l"(p));
    return a;
}
__device__ __forceinline__ void ldsm4(uint32_t* r, uint32_t addr) {
    asm volatile("ldmatrix.sync.aligned.m8n8.x4.shared.b16 {%0,%1,%2,%3}, [%4];"
                 : "=r"(r[0]), "=r"(r[1]), "=r"(r[2]), "=r"(r[3]) : "r"(addr));
}
__device__ __forceinline__ void mma_f16(float* c, const uint32_t* a, uint32_t b0, uint32_t b1) {
    asm volatile("mma.sync.aligned.m16n8k16.row.col.f32.f16.f16.f32 "
                 "{%0,%1,%2,%3}, {%4,%5,%6,%7}, {%8,%9}, {%0,%1,%2,%3};"
                 : "+f"(c[0]), "+f"(c[1]), "+f"(c[2]), "+f"(c[3])
                 : "r"(a[0]), "r"(a[1]), "r"(a[2]), "r"(a[3]), "r"(b0), "r"(b1));
}
__device__ __forceinline__ void add8(float* a, uint4 v) {
    const __half2* h = reinterpret_cast<const __half2*>(&v);
#pragma unroll
    for (int i = 0; i < 4; i++) {
        float2 f = __half22float2(h[i]);
        a[2 * i] += f.x;
        a[2 * i + 1] += f.y;
    }
}

// Shared gather-aggregate core: 16 lanes x 16B slices over one node's in-edges.
// Returns fp32 acc[8] = hws[node] + sum_neighbors hws[s], for this lane's cols.
__device__ __forceinline__ void gather_node(const uint4* __restrict__ base, int node,
                                            int lane, const int* __restrict__ rowptr,
                                            const int* __restrict__ cnt,
                                            const int* __restrict__ adj, float* acc0) {
    float acc1[8];
#pragma unroll
    for (int i = 0; i < 8; i++) { acc0[i] = 0.f; acc1[i] = 0.f; }
    add8(acc0, base[(size_t)node * 16 + lane]);  // self-loop
    int j = rowptr[node];
    const int jend = j + cnt[node];
    for (; j + 3 < jend; j += 4) {
        int s0 = __ldg(&adj[j]);
        int s1 = __ldg(&adj[j + 1]);
        int s2 = __ldg(&adj[j + 2]);
        int s3 = __ldg(&adj[j + 3]);
        uint4 a = base[(size_t)s0 * 16 + lane];
        uint4 b = base[(size_t)s1 * 16 + lane];
        uint4 c = base[(size_t)s2 * 16 + lane];
        uint4 d = base[(size_t)s3 * 16 + lane];
        add8(acc0, a); add8(acc1, b); add8(acc0, c); add8(acc1, d);
    }
    for (; j + 1 < jend; j += 2) {
        int s0 = __ldg(&adj[j]);
        int s1 = __ldg(&adj[j + 1]);
        uint4 a = base[(size_t)s0 * 16 + lane];
        uint4 b = base[(size_t)s1 * 16 + lane];
        add8(acc0, a); add8(acc1, b);
    }
    if (j < jend) add8(acc0, base[(size_t)__ldg(&adj[j]) * 16 + lane]);
#pragma unroll
    for (int i = 0; i < 8; i++) acc0[i] += acc1[i];
}

// ---------------------------------------------------------------------------
// Prep: W^T fp16 for all layers + zero count + zero scan cursor  (one launch)
// ---------------------------------------------------------------------------
__global__ void k_prep(const float* __restrict__ W0, const float* __restrict__ W1,
                       const float* __restrict__ W2, __half* __restrict__ wt, int n) {
    int gi = blockIdx.x * blockDim.x + threadIdx.x;
    if (gi < 3 * DD * DD) {
        int layer = gi >> 14, idx = gi & 16383;
        const float* W = (layer == 0) ? W0 : (layer == 1) ? W1 : W2;
        int k = idx >> 7, nn = idx & 127;
        wt[layer * DD * DD + nn * DD + k] = __float2half(W[idx]);
    }
    if (gi < n) g_count[gi] = 0;
    if (gi == 0) g_scanbase = 0;
}

__global__ void k_count(const int* __restrict__ dst, int e) {
    int i = blockIdx.x * blockDim.x + threadIdx.x;
    if (i < e) atomicAdd(&g_count[dst[i]], 1);
}

// One-pass offsets: per-chunk smem scan; chunk base via atomicAdd (arrival
// order — valid because aggregate reads (rowptr[w], count[w]), not rowptr[w+1]).
__global__ void k_offsets(int n) {
    __shared__ int s[256];
    __shared__ int basev;
    const int tid = threadIdx.x;
    const int base4 = blockIdx.x * CHUNK + tid * 4;
    int v0 = 0, v1 = 0, v2 = 0, v3 = 0;
    if (base4 + 0 < n) { v0 = g_count[base4 + 0]; g_dinv[base4 + 0] = rsqrtf((float)v0 + 1.f); }
    if (base4 + 1 < n) { v1 = g_count[base4 + 1]; g_dinv[base4 + 1] = rsqrtf((float)v1 + 1.f); }
    if (base4 + 2 < n) { v2 = g_count[base4 + 2]; g_dinv[base4 + 2] = rsqrtf((float)v2 + 1.f); }
    if (base4 + 3 < n) { v3 = g_count[base4 + 3]; g_dinv[base4 + 3] = rsqrtf((float)v3 + 1.f); }
    int tsum = v0 + v1 + v2 + v3;
    s[tid] = tsum;
    __syncthreads();
#pragma unroll
    for (int off = 1; off < 256; off <<= 1) {
        int tmp = (tid >= off) ? s[tid - off] : 0;
        __syncthreads();
        s[tid] += tmp;
        __syncthreads();
    }
    if (tid == 255) basev = atomicAdd(&g_scanbase, s[255]);
    __syncthreads();
    int excl = basev + s[tid] - tsum;
    if (base4 + 0 < n) { g_rowptr[base4 + 0] = excl;              g_cursor[base4 + 0] = excl; }
    if (base4 + 1 < n) { g_rowptr[base4 + 1] = excl + v0;         g_cursor[base4 + 1] = excl + v0; }
    if (base4 + 2 < n) { g_rowptr[base4 + 2] = excl + v0 + v1;    g_cursor[base4 + 2] = excl + v0 + v1; }
    if (base4 + 3 < n) { g_rowptr[base4 + 3] = excl + v0 + v1 + v2; g_cursor[base4 + 3] = excl + v0 + v1 + v2; }
}

__global__ void k_fill(const int* __restrict__ src, const int* __restrict__ dst, int e) {
    int i = blockIdx.x * blockDim.x + threadIdx.x;
    if (i < e) {
        int pos = atomicAdd(&g_cursor[dst[i]], 1);
        g_adj[pos] = src[i];
    }
}

// ---------------------------------------------------------------------------
// GEMM mainloop + epilogue (shared by both GEMM kernels).
// 256 threads / 8 warps; block 128x128; warp tile 32 rows x 64 cols.
// ---------------------------------------------------------------------------
__device__ __forceinline__ void gemm_core(char* smem, int tid, int row0,
                                          const float* __restrict__ dinv,
                                          __half* __restrict__ hws, int n) {
    const uint32_t sb = smem_u32(smem);
    const int w = tid >> 5, lane = tid & 31;
    const int mg = w >> 1, cg = w & 1;
    const int g = lane >> 2, tg = lane & 3;

    const uint32_t aAddr = sb + SA +
        (uint32_t)(mg * 32 + (lane & 15)) * PAD + (uint32_t)(lane >> 4) * 16;
    const uint32_t bAddr = sb + SW +
        (uint32_t)(cg * 64 + ((lane >> 4) & 1) * 8 + (lane & 7)) * PAD +
        (uint32_t)((lane >> 3) & 1) * 16;

    float acc[16][4];
#pragma unroll
    for (int t = 0; t < 16; t++)
#pragma unroll
        for (int j = 0; j < 4; j++) acc[t][j] = 0.f;

#pragma unroll
    for (int kk = 0; kk < 8; kk++) {
        uint32_t a0[4], a1[4];
        ldsm4(a0, aAddr + kk * 32);
        ldsm4(a1, aAddr + 16 * PAD + kk * 32);
#pragma unroll
        for (int np = 0; np < 4; np++) {
            uint32_t b[4];
            ldsm4(b, bAddr + (uint32_t)np * (16 * PAD) + kk * 32);
            mma_f16(acc[np * 2 + 0], a0, b[0], b[1]);
            mma_f16(acc[np * 2 + 1], a0, b[2], b[3]);
            mma_f16(acc[8 + np * 2 + 0], a1, b[0], b[1]);
            mma_f16(acc[8 + np * 2 + 1], a1, b[2], b[3]);
        }
    }

    const int rbase = row0 + mg * 32 + g;
#pragma unroll
    for (int ms = 0; ms < 2; ms++) {
        const int rA = rbase + ms * 16;
        const int rB = rA + 8;
        const float diA = (rA < n) ? dinv[rA] : 0.f;
        const float diB = (rB < n) ? dinv[rB] : 0.f;
#pragma unroll
        for (int np = 0; np < 4; np++) {
#pragma unroll
            for (int h = 0; h < 2; h++) {
                const float* cf = acc[ms * 8 + np * 2 + h];
                const int col = cg * 64 + np * 16 + h * 8 + tg * 2;
                if (rA < n) {
                    __half2 hv = __floats2half2_rn(cf[0] * diA, cf[1] * diA);
                    *reinterpret_cast<__half2*>(hws + (size_t)rA * DD + col) = hv;
                }
                if (rB < n) {
                    __half2 hv = __floats2half2_rn(cf[2] * diB, cf[3] * diB);
                    *reinterpret_cast<__half2*>(hws + (size_t)rB * DD + col) = hv;
                }
            }
        }
    }
}

__device__ __forceinline__ void stage_w(char* smem, int tid, const __half* __restrict__ wt) {
    const float4* w4 = reinterpret_cast<const float4*>(wt);
#pragma unroll
    for (int i = 0; i < 8; i++) {
        int chunk = i * 256 + tid;
        int r = chunk >> 4, c = chunk & 15;
        *reinterpret_cast<float4*>(smem + SW + r * PAD + c * 16) = w4[chunk];
    }
}

// ---------------------------------------------------------------------------
// Layer-0 GEMM: A = fp32 x, converted during staging.
// ---------------------------------------------------------------------------
__global__ void __launch_bounds__(256, 2)
k_gemm0(const float* __restrict__ Hf, const __half* __restrict__ wt,
        const float* __restrict__ dinv, __half* __restrict__ hws, int n) {
    extern __shared__ char smem[];
    const int tid = threadIdx.x;
    const int row0 = blockIdx.x * 128;

    stage_w(smem, tid, wt);
    {
        const float4* H4 = reinterpret_cast<const float4*>(Hf);
        const int maxc = (n - row0) * 32;
#pragma unroll
        for (int i = 0; i < 16; i++) {
            int chunk = i * 256 + tid;
            int r = chunk >> 5, c = chunk & 31;
            float4 v = make_float4(0.f, 0.f, 0.f, 0.f);
            if (chunk < maxc) v = H4[(size_t)row0 * 32 + chunk];
            __half2 h01 = __floats2half2_rn(v.x, v.y);
            __half2 h23 = __floats2half2_rn(v.z, v.w);
            uint2 hp;
            hp.x = *reinterpret_cast<uint32_t*>(&h01);
            hp.y = *reinterpret_cast<uint32_t*>(&h23);
            *reinterpret_cast<uint2*>(smem + SA + r * PAD + c * 8) = hp;
        }
    }
    __syncthreads();
    gemm_core(smem, tid, row0, dinv, hws, n);
}

// ---------------------------------------------------------------------------
// Fused aggregate + GEMM: A-tile = fp16(relu(dinv*(gather(hin)) + b)) built
// in smem directly (no aggh global round-trip), then GEMM with W -> hout.
// 16 half-warps x 8 iterations cover the 128-row tile.
// ---------------------------------------------------------------------------
__global__ void __launch_bounds__(256, 2)
k_agg_gemm(const __half* __restrict__ hin, const int* __restrict__ rowptr,
           const int* __restrict__ cnt, const int* __restrict__ adj,
           const float* __restrict__ dinv, const float* __restrict__ bias,
           const __half* __restrict__ wt, __half* __restrict__ hout, int n) {
    extern __shared__ char smem[];
    const int tid = threadIdx.x;
    const int row0 = blockIdx.x * 128;

    stage_w(smem, tid, wt);

    const int hw = tid >> 4;        // half-warp 0..15
    const int lane = tid & 15;
    const int col = lane * 8;
    const float4* bp = reinterpret_cast<const float4*>(bias + col);
    const float4 b0 = bp[0], b1 = bp[1];
    const float b8[8] = {b0.x, b0.y, b0.z, b0.w, b1.x, b1.y, b1.z, b1.w};
    const uint4* base = reinterpret_cast<const uint4*>(hin);

#pragma unroll 1
    for (int it = 0; it < 8; it++) {
        const int r = it * 16 + hw;
        const int node = row0 + r;
        uint4 hv = make_uint4(0u, 0u, 0u, 0u);
        if (node < n) {
            float acc[8];
            gather_node(base, node, lane, rowptr, cnt, adj, acc);
            const float di = dinv[node];
            uint32_t* hp = reinterpret_cast<uint32_t*>(&hv);
#pragma unroll
            for (int i = 0; i < 4; i++) {
                float o0 = fmaxf(fmaf(acc[2 * i], di, b8[2 * i]), 0.f);
                float o1 = fmaxf(fmaf(acc[2 * i + 1], di, b8[2 * i + 1]), 0.f);
                __half2 h2 = __floats2half2_rn(o0, o1);
                hp[i] = *reinterpret_cast<uint32_t*>(&h2);
            }
        }
        *reinterpret_cast<uint4*>(smem + SA + r * PAD + lane * 16) = hv;
    }
    __syncthreads();
    gemm_core(smem, tid, row0, dinv, hout, n);
}

// ---------------------------------------------------------------------------
// Final aggregate: out = dinv*(gather(hws)) + b + x   (fp32, d_out)
// ---------------------------------------------------------------------------
__global__ void k_agg_final(const __half* __restrict__ hws, const int* __restrict__ rowptr,
                            const int* __restrict__ cnt, const int* __restrict__ adj,
                            const float* __restrict__ dinv, const float* __restrict__ bias,
                            const float* __restrict__ xres, float* __restrict__ out, int n) {
    int w = (blockIdx.x * blockDim.x + threadIdx.x) >> 4;
    if (w >= n) return;
    const int lane = threadIdx.x & 15;

    float acc[8];
    gather_node(reinterpret_cast<const uint4*>(hws), w, lane, rowptr, cnt, adj, acc);

    const float di = dinv[w];
    const int col = lane * 8;
    float o[8];
#pragma unroll
    for (int i = 0; i < 8; i++) o[i] = fmaf(acc[i], di, bias[col + i]);
    const float4* xr = reinterpret_cast<const float4*>(xres + (size_t)w * DD + col);
    float4 x0 = xr[0], x1 = xr[1];
    o[0] += x0.x; o[1] += x0.y; o[2] += x0.z; o[3] += x0.w;
    o[4] += x1.x; o[5] += x1.y; o[6] += x1.z; o[7] += x1.w;
    float4* op = reinterpret_cast<float4*>(out + (size_t)w * DD + col);
    op[0] = make_float4(o[0], o[1], o[2], o[3]);
    op[1] = make_float4(o[4], o[5], o[6], o[7]);
}

// ---------------------------------------------------------------------------
extern "C" void kernel_launch(void* const* d_in, const int* in_sizes, int n_in,
                              void* d_out, int out_size) {
    const float* x  = (const float*)d_in[0];
    const int*   ei = (const int*)d_in[1];
    const float* W0 = (const float*)d_in[2];
    const float* b0 = (const float*)d_in[3];
    const float* W1 = (const float*)d_in[4];
    const float* b1 = (const float*)d_in[5];
    const float* W2 = (const float*)d_in[6];
    const float* b2 = (const float*)d_in[7];
    float* out = (float*)d_out;

    const int n = in_sizes[0] / DD;
    const int e = in_sizes[1] / 2;
    const int* src = ei;
    const int* dst = ei + e;

    float* d_dinv;
    __half *d_hA, *d_hB, *d_wt;
    int *d_count, *d_rowptr, *d_adj;
    cudaGetSymbolAddress((void**)&d_hA, g_hwsA);
    cudaGetSymbolAddress((void**)&d_hB, g_hwsB);
    cudaGetSymbolAddress((void**)&d_dinv, g_dinv);
    cudaGetSymbolAddress((void**)&d_count, g_count);
    cudaGetSymbolAddress((void**)&d_rowptr, g_rowptr);
    cudaGetSymbolAddress((void**)&d_adj, g_adj);
    cudaGetSymbolAddress((void**)&d_wt, g_wt);

    cudaFuncSetAttribute(k_gemm0,    cudaFuncAttributeMaxDynamicSharedMemorySize, SM_TOT);
    cudaFuncSetAttribute(k_agg_gemm, cudaFuncAttributeMaxDynamicSharedMemorySize, SM_TOT);

    const int TB = 256;
    const int nb_e = (e + TB - 1) / TB;
    const int nb_gemm = (n + 127) / 128;
    const int nchunks = (n + CHUNK - 1) / CHUNK;
    const int nb_prep = (((3 * DD * DD > n) ? 3 * DD * DD : n) + TB - 1) / TB;
    const long long agg_threads = (long long)n * 16;
    const int nb_agg = (int)((agg_threads + TB - 1) / TB);

    // Prep + CSR (4 launches)
    k_prep<<<nb_prep, TB>>>(W0, W1, W2, d_wt, n);
    k_count<<<nb_e, TB>>>(dst, e);
    k_offsets<<<nchunks, 256>>>(n);
    k_fill<<<nb_e, TB>>>(src, dst, e);

    // Layer 0: x @ W0 -> hA
    k_gemm0<<<nb_gemm, 256, SM_TOT>>>(x, d_wt, d_dinv, d_hA, n);
    // Layer 1: agg(hA)+b0,relu -> @W1 -> hB
    k_agg_gemm<<<nb_gemm, 256, SM_TOT>>>(d_hA, d_rowptr, d_count, d_adj, d_dinv, b0,
                                         d_wt + DD * DD, d_hB, n);
    // Layer 2: agg(hB)+b1,relu -> @W2 -> hA
    k_agg_gemm<<<nb_gemm, 256, SM_TOT>>>(d_hB, d_rowptr, d_count, d_adj, d_dinv, b1,
                                         d_wt + 2 * DD * DD, d_hA, n);
    // Final: agg(hA)+b2 + x -> out
    k_agg_final<<<nb_agg, TB>>>(d_hA, d_rowptr, d_count, d_adj, d_dinv, b2, x, out, n);
}

// round 16
// speedup vs baseline: 1.2795x; 1.2795x over previous
#include <cuda_runtime.h>
#include <cuda_fp16.h>
#include <math.h>
#include <cstdint>

#define NN 50000
#define EE 800000
#define DD 128
#define PAD 272                 // padded smem row stride (bytes): conflict-free ldmatrix
#define SA 0
#define SW 34816
#define SM_TOT 69632
#define CHUNK 1024

// ---- scratch (__device__ globals; allocation-free rule) ----
__device__ __half g_hwsh[(size_t)NN * DD];   // (h@W)*dinv, fp16 (gather payload)
__device__ __half g_aggh[(size_t)NN * DD];   // relu(aggregate), fp16 (next-layer input)
__device__ int    g_count[NN];
__device__ float  g_dinv[NN];
__device__ int    g_rowptr[NN];              // segment start (arrival-ordered)
__device__ int    g_cursor[NN];
__device__ int    g_adj[EE];
__device__ int    g_scanbase;                // global cursor for chunk bases
__device__ __half g_wt[3 * DD * DD];         // W^T fp16 ([n][k] row-major)

// ---- helpers ----
__device__ __forceinline__ uint32_t smem_u32(const void* p) {
    uint32_t a;
    asm("{ .reg .u64 t; cvta.to.shared.u64 t, %1; cvt.u32.u64 %0, t; }" : "=r"(a) : "l"(p));
    return a;
}
__device__ __forceinline__ void ldsm4(uint32_t* r, uint32_t addr) {
    asm volatile("ldmatrix.sync.aligned.m8n8.x4.shared.b16 {%0,%1,%2,%3}, [%4];"
                 : "=r"(r[0]), "=r"(r[1]), "=r"(r[2]), "=r"(r[3]) : "r"(addr));
}
__device__ __forceinline__ void mma_f16(float* c, const uint32_t* a, uint32_t b0, uint32_t b1) {
    asm volatile("mma.sync.aligned.m16n8k16.row.col.f32.f16.f16.f32 "
                 "{%0,%1,%2,%3}, {%4,%5,%6,%7}, {%8,%9}, {%0,%1,%2,%3};"
                 : "+f"(c[0]), "+f"(c[1]), "+f"(c[2]), "+f"(c[3])
                 : "r"(a[0]), "r"(a[1]), "r"(a[2]), "r"(a[3]), "r"(b0), "r"(b1));
}
__device__ __forceinline__ void add8(float* a, uint4 v) {
    const __half2* h = reinterpret_cast<const __half2*>(&v);
#pragma unroll
    for (int i = 0; i < 4; i++) {
        float2 f = __half22float2(h[i]);
        a[2 * i] += f.x;
        a[2 * i + 1] += f.y;
    }
}

// ---------------------------------------------------------------------------
// Prep: W^T fp16 for all layers + zero count + zero scan cursor  (one launch)
// ---------------------------------------------------------------------------
__global__ void k_prep(const float* __restrict__ W0, const float* __restrict__ W1,
                       const float* __restrict__ W2, __half* __restrict__ wt, int n) {
    int gi = blockIdx.x * blockDim.x + threadIdx.x;
    if (gi < 3 * DD * DD) {
        int layer = gi >> 14, idx = gi & 16383;
        const float* W = (layer == 0) ? W0 : (layer == 1) ? W1 : W2;
        int k = idx >> 7, nn = idx & 127;
        wt[layer * DD * DD + nn * DD + k] = __float2half(W[idx]);
    }
    if (gi < n) g_count[gi] = 0;
    if (gi == 0) g_scanbase = 0;
}

__global__ void k_count(const int* __restrict__ dst, int e) {
    int i = blockIdx.x * blockDim.x + threadIdx.x;
    if (i < e) atomicAdd(&g_count[dst[i]], 1);
}

// One-pass offsets: per-chunk smem scan; chunk base via atomicAdd (arrival
// order — valid because consumers read (rowptr[w], count[w]), not rowptr[w+1]).
__global__ void k_offsets(int n) {
    __shared__ int s[256];
    __shared__ int basev;
    const int tid = threadIdx.x;
    const int base4 = blockIdx.x * CHUNK + tid * 4;
    int v0 = 0, v1 = 0, v2 = 0, v3 = 0;
    if (base4 + 0 < n) { v0 = g_count[base4 + 0]; g_dinv[base4 + 0] = rsqrtf((float)v0 + 1.f); }
    if (base4 + 1 < n) { v1 = g_count[base4 + 1]; g_dinv[base4 + 1] = rsqrtf((float)v1 + 1.f); }
    if (base4 + 2 < n) { v2 = g_count[base4 + 2]; g_dinv[base4 + 2] = rsqrtf((float)v2 + 1.f); }
    if (base4 + 3 < n) { v3 = g_count[base4 + 3]; g_dinv[base4 + 3] = rsqrtf((float)v3 + 1.f); }
    int tsum = v0 + v1 + v2 + v3;
    s[tid] = tsum;
    __syncthreads();
#pragma unroll
    for (int off = 1; off < 256; off <<= 1) {
        int tmp = (tid >= off) ? s[tid - off] : 0;
        __syncthreads();
        s[tid] += tmp;
        __syncthreads();
    }
    if (tid == 255) basev = atomicAdd(&g_scanbase, s[255]);
    __syncthreads();
    int excl = basev + s[tid] - tsum;
    if (base4 + 0 < n) { g_rowptr[base4 + 0] = excl;                g_cursor[base4 + 0] = excl; }
    if (base4 + 1 < n) { g_rowptr[base4 + 1] = excl + v0;           g_cursor[base4 + 1] = excl + v0; }
    if (base4 + 2 < n) { g_rowptr[base4 + 2] = excl + v0 + v1;      g_cursor[base4 + 2] = excl + v0 + v1; }
    if (base4 + 3 < n) { g_rowptr[base4 + 3] = excl + v0 + v1 + v2; g_cursor[base4 + 3] = excl + v0 + v1 + v2; }
}

__global__ void k_fill(const int* __restrict__ src, const int* __restrict__ dst, int e) {
    int i = blockIdx.x * blockDim.x + threadIdx.x;
    if (i < e) {
        int pos = atomicAdd(&g_cursor[dst[i]], 1);
        g_adj[pos] = src[i];
    }
}

// ---------------------------------------------------------------------------
// Tensor-core GEMM (mma.sync fp16 single-pass, fp32 accum):
//   hwsh[row] = half((H[row] @ W) * dinv[row])
// 256 threads / 8 warps; block 128x128; warp tile 32 rows x 64 cols.
// (round-13 verified kernel, unchanged)
// ---------------------------------------------------------------------------
template <bool INHALF>
__global__ void __launch_bounds__(256, 2)
k_gemm_mma(const float* __restrict__ Hf, const __half* __restrict__ Hh,
           const __half* __restrict__ wt, const float* __restrict__ dinv,
           __half* __restrict__ hws, int n) {
    extern __shared__ char smem[];
    const int tid = threadIdx.x;
    const int row0 = blockIdx.x * 128;

    // Stage W^T (fp16, 32KB) into padded smem
    {
        const float4* w4 = reinterpret_cast<const float4*>(wt);
#pragma unroll
        for (int i = 0; i < 8; i++) {
            int chunk = i * 256 + tid;
            int r = chunk >> 4, c = chunk & 15;
            *reinterpret_cast<float4*>(smem + SW + r * PAD + c * 16) = w4[chunk];
        }
    }
    // Stage A (fp16) into padded smem
    if (INHALF) {
        const uint4* H4 = reinterpret_cast<const uint4*>(Hh);
        const int maxc = (n - row0) * 16;
#pragma unroll
        for (int i = 0; i < 8; i++) {
            int chunk = i * 256 + tid;
            int r = chunk >> 4, c = chunk & 15;
            uint4 v = make_uint4(0u, 0u, 0u, 0u);
            if (chunk < maxc) v = H4[(size_t)row0 * 16 + chunk];
            *reinterpret_cast<uint4*>(smem + SA + r * PAD + c * 16) = v;
        }
    } else {
        const float4* H4 = reinterpret_cast<const float4*>(Hf);
        const int maxc = (n - row0) * 32;
#pragma unroll
        for (int i = 0; i < 16; i++) {
            int chunk = i * 256 + tid;
            int r = chunk >> 5, c = chunk & 31;
            float4 v = make_float4(0.f, 0.f, 0.f, 0.f);
            if (chunk < maxc) v = H4[(size_t)row0 * 32 + chunk];
            __half2 h01 = __floats2half2_rn(v.x, v.y);
            __half2 h23 = __floats2half2_rn(v.z, v.w);
            uint2 hp;
            hp.x = *reinterpret_cast<uint32_t*>(&h01);
            hp.y = *reinterpret_cast<uint32_t*>(&h23);
            *reinterpret_cast<uint2*>(smem + SA + r * PAD + c * 8) = hp;
        }
    }
    __syncthreads();

    const uint32_t sb = smem_u32(smem);
    const int w = tid >> 5, lane = tid & 31;
    const int mg = w >> 1, cg = w & 1;
    const int g = lane >> 2, tg = lane & 3;

    const uint32_t aAddr = sb + SA +
        (uint32_t)(mg * 32 + (lane & 15)) * PAD + (uint32_t)(lane >> 4) * 16;
    const uint32_t bAddr = sb + SW +
        (uint32_t)(cg * 64 + ((lane >> 4) & 1) * 8 + (lane & 7)) * PAD +
        (uint32_t)((lane >> 3) & 1) * 16;

    float acc[16][4];
#pragma unroll
    for (int t = 0; t < 16; t++)
#pragma unroll
        for (int j = 0; j < 4; j++) acc[t][j] = 0.f;

#pragma unroll
    for (int kk = 0; kk < 8; kk++) {
        uint32_t a0[4], a1[4];
        ldsm4(a0, aAddr + kk * 32);
        ldsm4(a1, aAddr + 16 * PAD + kk * 32);
#pragma unroll
        for (int np = 0; np < 4; np++) {
            uint32_t b[4];
            ldsm4(b, bAddr + (uint32_t)np * (16 * PAD) + kk * 32);
            mma_f16(acc[np * 2 + 0], a0, b[0], b[1]);
            mma_f16(acc[np * 2 + 1], a0, b[2], b[3]);
            mma_f16(acc[8 + np * 2 + 0], a1, b[0], b[1]);
            mma_f16(acc[8 + np * 2 + 1], a1, b[2], b[3]);
        }
    }

    const int rbase = row0 + mg * 32 + g;
#pragma unroll
    for (int ms = 0; ms < 2; ms++) {
        const int rA = rbase + ms * 16;
        const int rB = rA + 8;
        const float diA = (rA < n) ? dinv[rA] : 0.f;
        const float diB = (rB < n) ? dinv[rB] : 0.f;
#pragma unroll
        for (int np = 0; np < 4; np++) {
#pragma unroll
            for (int h = 0; h < 2; h++) {
                const float* cf = acc[ms * 8 + np * 2 + h];
                const int col = cg * 64 + np * 16 + h * 8 + tg * 2;
                if (rA < n) {
                    __half2 hv = __floats2half2_rn(cf[0] * diA, cf[1] * diA);
                    *reinterpret_cast<__half2*>(hws + (size_t)rA * DD + col) = hv;
                }
                if (rB < n) {
                    __half2 hv = __floats2half2_rn(cf[2] * diB, cf[3] * diB);
                    *reinterpret_cast<__half2*>(hws + (size_t)rB * DD + col) = hv;
                }
            }
        }
    }
}

// ---------------------------------------------------------------------------
// Pull-mode aggregate (fp16 gather, fp32 accumulate), standalone for
// occupancy (round-13 structure; segment addressing = rowptr[w] + count[w]).
//   t = dinv[d]*(hws[d] + sum_{s in in(d)} hws[s]) + b
//   FINAL=0: outh[d] = fp16(relu(t));   FINAL=1: outf[d] = t + x[d]
// ---------------------------------------------------------------------------
template <bool FINAL>
__global__ void k_aggregate(const __half* __restrict__ hws, const int* __restrict__ rowptr,
                            const int* __restrict__ cnt, const int* __restrict__ adj,
                            const float* __restrict__ dinv, const float* __restrict__ bias,
                            const float* __restrict__ xres,
                            __half* __restrict__ outh, float* __restrict__ outf, int n) {
    int w = (blockIdx.x * blockDim.x + threadIdx.x) >> 4;
    if (w >= n) return;
    const int lane = threadIdx.x & 15;

    const uint4* base = reinterpret_cast<const uint4*>(hws);
    float acc0[8], acc1[8];
#pragma unroll
    for (int i = 0; i < 8; i++) { acc0[i] = 0.f; acc1[i] = 0.f; }
    add8(acc0, base[(size_t)w * 16 + lane]);  // self-loop

    int j = rowptr[w];
    const int jend = j + cnt[w];
    for (; j + 3 < jend; j += 4) {
        int s0 = __ldg(&adj[j]);
        int s1 = __ldg(&adj[j + 1]);
        int s2 = __ldg(&adj[j + 2]);
        int s3 = __ldg(&adj[j + 3]);
        uint4 a = base[(size_t)s0 * 16 + lane];
        uint4 b = base[(size_t)s1 * 16 + lane];
        uint4 c = base[(size_t)s2 * 16 + lane];
        uint4 d = base[(size_t)s3 * 16 + lane];
        add8(acc0, a); add8(acc1, b); add8(acc0, c); add8(acc1, d);
    }
    for (; j + 1 < jend; j += 2) {
        int s0 = __ldg(&adj[j]);
        int s1 = __ldg(&adj[j + 1]);
        uint4 a = base[(size_t)s0 * 16 + lane];
        uint4 b = base[(size_t)s1 * 16 + lane];
        add8(acc0, a); add8(acc1, b);
    }
    if (j < jend) add8(acc0, base[(size_t)__ldg(&adj[j]) * 16 + lane]);
#pragma unroll
    for (int i = 0; i < 8; i++) acc0[i] += acc1[i];

    const float di = dinv[w];
    const int col = lane * 8;
    float o[8];
#pragma unroll
    for (int i = 0; i < 8; i++) o[i] = fmaf(acc0[i], di, bias[col + i]);

    if (FINAL) {
        const float4* xr = reinterpret_cast<const float4*>(xres + (size_t)w * DD + col);
        float4 x0 = xr[0], x1 = xr[1];
        o[0] += x0.x; o[1] += x0.y; o[2] += x0.z; o[3] += x0.w;
        o[4] += x1.x; o[5] += x1.y; o[6] += x1.z; o[7] += x1.w;
        float4* op = reinterpret_cast<float4*>(outf + (size_t)w * DD + col);
        op[0] = make_float4(o[0], o[1], o[2], o[3]);
        op[1] = make_float4(o[4], o[5], o[6], o[7]);
    } else {
        uint4 hv;
        uint32_t* hp = reinterpret_cast<uint32_t*>(&hv);
#pragma unroll
        for (int i = 0; i < 4; i++) {
            __half2 h2 = __floats2half2_rn(fmaxf(o[2 * i], 0.f), fmaxf(o[2 * i + 1], 0.f));
            hp[i] = *reinterpret_cast<uint32_t*>(&h2);
        }
        reinterpret_cast<uint4*>(outh)[(size_t)w * 16 + lane] = hv;
    }
}

// ---------------------------------------------------------------------------
extern "C" void kernel_launch(void* const* d_in, const int* in_sizes, int n_in,
                              void* d_out, int out_size) {
    const float* x  = (const float*)d_in[0];
    const int*   ei = (const int*)d_in[1];
    const float* W0 = (const float*)d_in[2];
    const float* b0 = (const float*)d_in[3];
    const float* W1 = (const float*)d_in[4];
    const float* b1 = (const float*)d_in[5];
    const float* W2 = (const float*)d_in[6];
    const float* b2 = (const float*)d_in[7];
    float* out = (float*)d_out;

    const int n = in_sizes[0] / DD;
    const int e = in_sizes[1] / 2;
    const int* src = ei;
    const int* dst = ei + e;

    float* d_dinv;
    __half *d_hws, *d_aggh, *d_wt;
    int *d_count, *d_rowptr, *d_adj;
    cudaGetSymbolAddress((void**)&d_hws, g_hwsh);
    cudaGetSymbolAddress((void**)&d_aggh, g_aggh);
    cudaGetSymbolAddress((void**)&d_dinv, g_dinv);
    cudaGetSymbolAddress((void**)&d_count, g_count);
    cudaGetSymbolAddress((void**)&d_rowptr, g_rowptr);
    cudaGetSymbolAddress((void**)&d_adj, g_adj);
    cudaGetSymbolAddress((void**)&d_wt, g_wt);

    cudaFuncSetAttribute(k_gemm_mma<false>, cudaFuncAttributeMaxDynamicSharedMemorySize, SM_TOT);
    cudaFuncSetAttribute(k_gemm_mma<true>,  cudaFuncAttributeMaxDynamicSharedMemorySize, SM_TOT);

    const int TB = 256;
    const int nb_e = (e + TB - 1) / TB;
    const int nb_gemm = (n + 127) / 128;
    const int nchunks = (n + CHUNK - 1) / CHUNK;
    const int nb_prep = (((3 * DD * DD > n) ? 3 * DD * DD : n) + TB - 1) / TB;
    const long long agg_threads = (long long)n * 16;
    const int nb_agg = (int)((agg_threads + TB - 1) / TB);

    // Prep + CSR (4 launches)
    k_prep<<<nb_prep, TB>>>(W0, W1, W2, d_wt, n);
    k_count<<<nb_e, TB>>>(dst, e);
    k_offsets<<<nchunks, 256>>>(n);
    k_fill<<<nb_e, TB>>>(src, dst, e);

    // Layer 0 (fp32 input x)
    k_gemm_mma<false><<<nb_gemm, 256, SM_TOT>>>(x, nullptr, d_wt, d_dinv, d_hws, n);
    k_aggregate<false><<<nb_agg, TB>>>(d_hws, d_rowptr, d_count, d_adj, d_dinv, b0,
                                       nullptr, d_aggh, nullptr, n);
    // Layer 1 (fp16 input, relu pre-applied)
    k_gemm_mma<true><<<nb_gemm, 256, SM_TOT>>>(nullptr, d_aggh, d_wt + DD * DD, d_dinv, d_hws, n);
    k_aggregate<false><<<nb_agg, TB>>>(d_hws, d_rowptr, d_count, d_adj, d_dinv, b1,
                                       nullptr, d_aggh, nullptr, n);
    // Layer 2 (fp16 input; +x residual fp32 -> d_out)
    k_gemm_mma<true><<<nb_gemm, 256, SM_TOT>>>(nullptr, d_aggh, d_wt + 2 * DD * DD, d_dinv, d_hws, n);
    k_aggregate<true><<<nb_agg, TB>>>(d_hws, d_rowptr, d_count, d_adj, d_dinv, b2,
                                      x, nullptr, out, n);
}